// round 1
// baseline (speedup 1.0000x reference)
#include <cuda_runtime.h>

// Problem constants (fixed-shape problem)
#define HH 352
#define WW 1216
#define PP 65536
#define CC 64
#define BB 2

// r = RADIUS_PX / max(H,W) * 2 = 3/1216 (NDC). hy=1, hx=2 window.
// Geometric facts: at most ONE row and at most THREE columns can have
// pixel centers within distance r of the point -> <=3 covered pixels.

__global__ void __launch_bounds__(256)
splat_kernel(const float* __restrict__ pts,
             const float* __restrict__ src,
             float* __restrict__ out) {
    int t = blockIdx.x * blockDim.x + threadIdx.x;
    if (t >= BB * PP) return;
    int b = t >> 16;          // t / PP  (PP = 65536)
    int p = t & (PP - 1);

    float x = pts[3 * t + 0];
    float y = pts[3 * t + 1];
    float z = pts[3 * t + 2];

    const float r  = 3.0f / 1216.0f;
    const float r2 = r * r;
    const float inv_r2 = 1216.0f * 1216.0f / 9.0f;   // 1/r^2 (RAD_POW=2)

    int i0 = (int)floorf((y + 1.0f) * 0.5f * (float)HH);
    int j0 = (int)floorf((x + 1.0f) * 0.5f * (float)WW);

    int   pix[4];
    float wts[4];
    int nv = 0;

    if (z > 0.0f) {
        #pragma unroll
        for (int dy = -1; dy <= 1; dy++) {
            int ii = i0 + dy;
            if (ii < 0 || ii >= HH) continue;
            float yc  = ((float)ii + 0.5f) * (2.0f / (float)HH) - 1.0f;
            float fy  = y - yc;
            float fy2 = fy * fy;
            #pragma unroll
            for (int dx = -2; dx <= 2; dx++) {
                int jj = j0 + dx;
                if (jj < 0 || jj >= WW) continue;
                float xc = ((float)jj + 0.5f) * (2.0f / (float)WW) - 1.0f;
                float fx = x - xc;
                float d2 = fx * fx + fy2;
                if (d2 < r2 && nv < 4) {
                    // dist = d2 / r^2 ; clip(dist, 0.001, 1) ; alpha = 1 - sqrt(dist)
                    float dist  = d2 * inv_r2;
                    float alpha = 1.0f - sqrtf(fmaxf(dist, 0.001f));
                    pix[nv] = ii * WW + jj;
                    wts[nv] = alpha;
                    nv++;
                }
            }
        }
    }

    if (nv == 0) return;

    const float* sp = src + (size_t)b * CC * PP + p;     // src[b, c, p], stride P over c
    float*       ob = out + (size_t)b * CC * (HH * WW);  // out[b, c, i, j]

    #pragma unroll 8
    for (int c = 0; c < CC; c++) {
        float  f  = sp[(size_t)c * PP];                  // coalesced across warp (p contiguous)
        float* oc = ob + (size_t)c * (HH * WW);
        for (int v = 0; v < nv; v++)
            atomicAdd(oc + pix[v], wts[v] * f);
    }
}

extern "C" void kernel_launch(void* const* d_in, const int* in_sizes, int n_in,
                              void* d_out, int out_size) {
    const float* pts = (const float*)d_in[0];   // [B, P, 3] float32
    const float* src = (const float*)d_in[1];   // [B, C, P] float32
    float* out = (float*)d_out;                 // [B, C, H, W] float32

    // Output is poisoned 0xAA — zero it (async memset is graph-capturable).
    cudaMemsetAsync(out, 0, (size_t)out_size * sizeof(float), 0);

    int total   = BB * PP;                       // 131072 points
    int threads = 256;
    int blocks  = (total + threads - 1) / threads;
    splat_kernel<<<blocks, threads>>>(pts, src, out);
}

// round 2
// speedup vs baseline: 1.5094x; 1.5094x over previous
#include <cuda_runtime.h>

// Fixed-shape problem constants
#define HH 352
#define WW 1216
#define PP 65536
#define CC 64
#define BB 2
#define HW (HH * WW)

// r = RADIUS_PX/max(H,W)*2 = 3/1216 NDC.
// Row pitch 2/352=0.00568 > 2r=0.00493  -> only the containing row i0 can pass
//   (its center is always the nearest row center; half-pitch 0.00284 > r).
// Col pitch 2/1216, 2r spans <=3 centers -> only j0-1, j0, j0+1 can pass.

#define GROUPS 8            // threads per point
#define CPT (CC / GROUPS)   // channels per thread = 8

__global__ void __launch_bounds__(256)
zero_kernel(float4* __restrict__ out, int n4) {
    int t = blockIdx.x * blockDim.x + threadIdx.x;
    if (t < n4) out[t] = make_float4(0.f, 0.f, 0.f, 0.f);
}

__global__ void __launch_bounds__(256)
splat_kernel(const float* __restrict__ pts,
             const float* __restrict__ src,
             float* __restrict__ out) {
    int tid = blockIdx.x * blockDim.x + threadIdx.x;
    int t = tid & (BB * PP - 1);        // point index (lane-contiguous -> coalesced)
    int g = tid >> 17;                  // channel group 0..7
    int b = t >> 16;
    int p = t & (PP - 1);

    float x = pts[3 * t + 0];
    float y = pts[3 * t + 1];
    float z = pts[3 * t + 2];

    const float r2     = (3.0f / 1216.0f) * (3.0f / 1216.0f);
    const float inv_r2 = 1216.0f * 1216.0f / 9.0f;

    int i0 = (int)floorf((y + 1.0f) * 0.5f * (float)HH);
    int j0 = (int)floorf((x + 1.0f) * 0.5f * (float)WW);

    float w0 = 0.f, w1 = 0.f, w2 = 0.f;
    if (z > 0.0f && i0 >= 0 && i0 < HH) {
        float yc  = ((float)i0 + 0.5f) * (2.0f / (float)HH) - 1.0f;
        float fy2 = (y - yc) * (y - yc);
        #pragma unroll
        for (int dxi = -1; dxi <= 1; dxi++) {
            int jj = j0 + dxi;
            if (jj < 0 || jj >= WW) continue;
            float xc = ((float)jj + 0.5f) * (2.0f / (float)WW) - 1.0f;
            float fx = x - xc;
            float d2 = fx * fx + fy2;
            if (d2 < r2) {
                float alpha = 1.0f - sqrtf(fmaxf(d2 * inv_r2, 0.001f));
                if (dxi < 0) w0 = alpha; else if (dxi == 0) w1 = alpha; else w2 = alpha;
            }
        }
    }
    if (w0 == 0.f && w1 == 0.f && w2 == 0.f) return;

    int pixb = i0 * WW + j0;
    const float* sp = src + (size_t)b * CC * PP + (size_t)(g * CPT) * PP + p;
    float*       ob = out + (size_t)b * CC * HW + (size_t)(g * CPT) * HW + pixb;

    // Prefetch all CPT feature values first (MLP), then fire atomics.
    float f[CPT];
    #pragma unroll
    for (int c = 0; c < CPT; c++) f[c] = sp[(size_t)c * PP];

    #pragma unroll
    for (int c = 0; c < CPT; c++) {
        float* oc = ob + (size_t)c * HW;
        if (w0 != 0.f) atomicAdd(oc - 1, w0 * f[c]);
        if (w1 != 0.f) atomicAdd(oc,     w1 * f[c]);
        if (w2 != 0.f) atomicAdd(oc + 1, w2 * f[c]);
    }
}

extern "C" void kernel_launch(void* const* d_in, const int* in_sizes, int n_in,
                              void* d_out, int out_size) {
    const float* pts = (const float*)d_in[0];   // [B, P, 3]
    const float* src = (const float*)d_in[1];   // [B, C, P]
    float* out = (float*)d_out;                 // [B, C, H, W]

    int n4 = out_size / 4;                      // out_size = 54,788,096 (divisible by 4)
    zero_kernel<<<(n4 + 255) / 256, 256>>>((float4*)out, n4);

    int total   = GROUPS * BB * PP;             // 1,048,576 threads
    int blocks  = total / 256;                  // 4096 blocks
    splat_kernel<<<blocks, 256>>>(pts, src, out);
}

// round 3
// speedup vs baseline: 2.6251x; 1.7391x over previous
#include <cuda_runtime.h>
#include <stdint.h>

// Fixed-shape problem constants
#define HH 352
#define WW 1216
#define PP 65536
#define CC 64
#define BB 2
#define HW (HH * WW)            // 428032
#define NPIX (BB * HW)          // 856064
#define MAXC 8                  // per-pixel candidate capacity (matches reference K)

// Scratch (__device__ globals: allocation-free)
__device__ int    d_count[NPIX];
__device__ uint2  d_cand[NPIX * MAXC];          // {pid, bitcast(weight)}
__device__ float  d_featsT[BB * PP * CC];       // src transposed to [B*P, C]

// ---------------------------------------------------------------- zero counts
__global__ void __launch_bounds__(256)
zero_counts_kernel() {
    int t = blockIdx.x * blockDim.x + threadIdx.x;
    int4* p = (int4*)d_count;
    if (t < NPIX / 4) p[t] = make_int4(0, 0, 0, 0);
}

// ---------------------------------------------------------------- transpose
// src [B, C, P] -> d_featsT [B*P, C], 32x32 smem tiles.
__global__ void __launch_bounds__(256)
transpose_kernel(const float* __restrict__ src) {
    __shared__ float tile[32][33];
    int b     = blockIdx.z;
    int pbase = blockIdx.x * 32;
    int cbase = blockIdx.y * 32;
    const float* sb = src + (size_t)b * CC * PP;

    #pragma unroll
    for (int j = 0; j < 4; j++) {
        int c = cbase + threadIdx.y + j * 8;
        tile[threadIdx.y + j * 8][threadIdx.x] = sb[(size_t)c * PP + pbase + threadIdx.x];
    }
    __syncthreads();
    float* ob = d_featsT + ((size_t)b * PP) * CC;
    #pragma unroll
    for (int j = 0; j < 4; j++) {
        int p = pbase + threadIdx.y + j * 8;
        ob[(size_t)p * CC + cbase + threadIdx.x] = tile[threadIdx.x][threadIdx.y + j * 8];
    }
}

// ---------------------------------------------------------------- build lists
// r = 3/1216 NDC. Row pitch 2/352 > 2r -> only row i0 qualifies.
// Col pitch 2/1216, 2r spans <=3 centers -> only j0-1..j0+1.
__global__ void __launch_bounds__(256)
build_kernel(const float* __restrict__ pts) {
    int t = blockIdx.x * blockDim.x + threadIdx.x;
    if (t >= BB * PP) return;
    int b = t >> 16;

    float x = pts[3 * t + 0];
    float y = pts[3 * t + 1];
    float z = pts[3 * t + 2];

    const float r2     = (3.0f / 1216.0f) * (3.0f / 1216.0f);
    const float inv_r2 = 1216.0f * 1216.0f / 9.0f;

    int i0 = (int)floorf((y + 1.0f) * 0.5f * (float)HH);
    int j0 = (int)floorf((x + 1.0f) * 0.5f * (float)WW);

    if (!(z > 0.0f) || i0 < 0 || i0 >= HH) return;

    float yc  = ((float)i0 + 0.5f) * (2.0f / (float)HH) - 1.0f;
    float fy2 = (y - yc) * (y - yc);

    #pragma unroll
    for (int dxi = -1; dxi <= 1; dxi++) {
        int jj = j0 + dxi;
        if (jj < 0 || jj >= WW) continue;
        float xc = ((float)jj + 0.5f) * (2.0f / (float)WW) - 1.0f;
        float fx = x - xc;
        float d2 = fx * fx + fy2;
        if (d2 < r2) {
            float alpha = 1.0f - sqrtf(fmaxf(d2 * inv_r2, 0.001f));
            int pix = (b * HH + i0) * WW + jj;
            int idx = atomicAdd(&d_count[pix], 1);
            if (idx < MAXC)
                d_cand[pix * MAXC + idx] = make_uint2((unsigned)t, __float_as_uint(alpha));
        }
    }
}

// ---------------------------------------------------------------- gather
// grid: (NPIX/256, 8). Thread = one pixel x 8 channels. Plain coalesced stores.
__global__ void __launch_bounds__(256)
gather_kernel(float* __restrict__ out) {
    int pix = blockIdx.x * 256 + threadIdx.x;
    int g   = blockIdx.y;

    int n = d_count[pix];
    n = n < MAXC ? n : MAXC;

    float acc[8] = {0.f, 0.f, 0.f, 0.f, 0.f, 0.f, 0.f, 0.f};
    for (int i = 0; i < n; i++) {
        uint2 e = d_cand[pix * MAXC + i];
        float w = __uint_as_float(e.y);
        const float4* fp = (const float4*)(d_featsT + (size_t)e.x * CC + g * 8);
        float4 a = fp[0];
        float4 c = fp[1];
        acc[0] += w * a.x; acc[1] += w * a.y; acc[2] += w * a.z; acc[3] += w * a.w;
        acc[4] += w * c.x; acc[5] += w * c.y; acc[6] += w * c.z; acc[7] += w * c.w;
    }

    int b   = pix / HW;
    int loc = pix - b * HW;
    float* ob = out + (size_t)b * CC * HW + (size_t)(g * 8) * HW + loc;
    #pragma unroll
    for (int c = 0; c < 8; c++)
        ob[(size_t)c * HW] = acc[c];
}

extern "C" void kernel_launch(void* const* d_in, const int* in_sizes, int n_in,
                              void* d_out, int out_size) {
    const float* pts = (const float*)d_in[0];   // [B, P, 3]
    const float* src = (const float*)d_in[1];   // [B, C, P]
    float* out = (float*)d_out;                 // [B, C, H, W]

    zero_counts_kernel<<<(NPIX / 4 + 255) / 256, 256>>>();

    dim3 tthreads(32, 8);
    dim3 tgrid(PP / 32, CC / 32, BB);
    transpose_kernel<<<tgrid, tthreads>>>(src);

    build_kernel<<<(BB * PP) / 256, 256>>>(pts);

    dim3 ggrid(NPIX / 256, 8);                  // 856064 % 256 == 0
    gather_kernel<<<ggrid, 256>>>(out);
}